// round 2
// baseline (speedup 1.0000x reference)
#include <cuda_runtime.h>
#include <math.h>
#include <stdint.h>

#define BB   32
#define SS   200
#define SM1  199
#define MTOT (BB*SM1)   // 6368
#define MC   4

// ---------------- device-global scratch (allocation-free rule) ----------------
__device__ float d_emb_qc[(size_t)BB*SS*512];
__device__ float d_qca[(size_t)MTOT*1024];
__device__ float d_gx[(size_t)MTOT*1024];
__device__ float d_hall[(size_t)MTOT*256];
__device__ float d_hnext[(size_t)MTOT*768];
__device__ float d_hq[(size_t)MTOT*768];
__device__ float d_hc[(size_t)MTOT*768];
__device__ float d_hqa[(size_t)MTOT*256];
__device__ float d_hca[(size_t)MTOT*256];
__device__ float d_hstate[2][BB*256];
__device__ unsigned g_bar_count;
__device__ unsigned g_bar_gen;

__device__ __forceinline__ float sigmoidf_(float x) { return 1.f / (1.f + expf(-x)); }

__global__ void init_kernel() {
    if (threadIdx.x == 0) { g_bar_count = 0u; g_bar_gen = 0u; }
    for (int i = threadIdx.x; i < BB*256; i += blockDim.x) d_hstate[0][i] = 0.f;
}

// ---------------- embeddings + LSTM-input assembly ----------------
__global__ void embed_kernel(const int* __restrict__ q, const int* __restrict__ c,
                             const int* __restrict__ r,
                             const float* __restrict__ que_emb,
                             const float* __restrict__ concept_emb) {
    int bs = blockIdx.x;            // b*SS + s
    int b = bs / SS, s = bs % SS;
    int e = threadIdx.x;            // 0..255
    int qi = q[bs];
    float eq = que_emb[(size_t)qi*256 + e];
    float sum = 0.f; int cnt = 0;
    #pragma unroll
    for (int j = 0; j < MC; j++) {
        int cj = c[bs*MC + j];
        if (cj >= 0) { sum += concept_emb[(size_t)cj*256 + e]; cnt++; }
    }
    float ec = sum / (float)max(cnt, 1);
    size_t base = (size_t)bs * 512;
    d_emb_qc[base + e]       = eq;
    d_emb_qc[base + 256 + e] = ec;
    if (s < SM1) {
        float f1 = (float)r[bs];
        float f0 = 1.f - f1;
        size_t mb = ((size_t)b*SM1 + s) * 1024;
        d_qca[mb + e]       = eq * f0;
        d_qca[mb + 256 + e] = ec * f0;
        d_qca[mb + 512 + e] = eq * f1;
        d_qca[mb + 768 + e] = ec * f1;
    }
}

// ---------------- hnext = [emb_qc_shift | h] ----------------
__global__ void hnext_kernel() {
    int m = blockIdx.x;             // b*SM1 + t
    int b = m / SM1, t = m % SM1;
    int e = threadIdx.x;
    size_t src = ((size_t)b*SS + (t+1)) * 512;
    d_hnext[(size_t)m*768 + e]       = d_emb_qc[src + e];
    d_hnext[(size_t)m*768 + 256 + e] = d_emb_qc[src + 256 + e];
    d_hnext[(size_t)m*768 + 512 + e] = d_hall[(size_t)m*256 + e];
}

// ---------------- NT SGEMM: C[M,N] = A[M,K]*B[N,K]^T + bias (+bias2), opt ReLU
__global__ __launch_bounds__(256) void sgemm_nt(
    const float* __restrict__ A, const float* __restrict__ B,
    const float* __restrict__ bias, const float* __restrict__ bias2,
    float* __restrict__ C, int M, int N, int K, int relu)
{
    const int BM = 128, BN = 128, BK = 8;
    __shared__ float As[BK][BM + 4];
    __shared__ float Bs[BK][BN + 4];
    int tid = threadIdx.x;
    int tx = tid & 15, ty = tid >> 4;
    int m0 = blockIdx.y * BM, n0 = blockIdx.x * BN;

    float acc[8][8];
    #pragma unroll
    for (int i = 0; i < 8; i++)
        #pragma unroll
        for (int j = 0; j < 8; j++) acc[i][j] = 0.f;

    int lrow = tid >> 1;
    int lkg  = (tid & 1) << 2;

    for (int k0 = 0; k0 < K; k0 += BK) {
        float4 va = make_float4(0.f, 0.f, 0.f, 0.f);
        if (m0 + lrow < M)
            va = *reinterpret_cast<const float4*>(&A[(size_t)(m0 + lrow) * K + k0 + lkg]);
        As[lkg + 0][lrow] = va.x; As[lkg + 1][lrow] = va.y;
        As[lkg + 2][lrow] = va.z; As[lkg + 3][lrow] = va.w;

        float4 vb = *reinterpret_cast<const float4*>(&B[(size_t)(n0 + lrow) * K + k0 + lkg]);
        Bs[lkg + 0][lrow] = vb.x; Bs[lkg + 1][lrow] = vb.y;
        Bs[lkg + 2][lrow] = vb.z; Bs[lkg + 3][lrow] = vb.w;
        __syncthreads();

        #pragma unroll
        for (int kk = 0; kk < BK; kk++) {
            float a[8], bv[8];
            *reinterpret_cast<float4*>(&a[0])  = *reinterpret_cast<const float4*>(&As[kk][ty*8]);
            *reinterpret_cast<float4*>(&a[4])  = *reinterpret_cast<const float4*>(&As[kk][ty*8 + 4]);
            *reinterpret_cast<float4*>(&bv[0]) = *reinterpret_cast<const float4*>(&Bs[kk][tx*8]);
            *reinterpret_cast<float4*>(&bv[4]) = *reinterpret_cast<const float4*>(&Bs[kk][tx*8 + 4]);
            #pragma unroll
            for (int i = 0; i < 8; i++)
                #pragma unroll
                for (int j = 0; j < 8; j++)
                    acc[i][j] = fmaf(a[i], bv[j], acc[i][j]);
        }
        __syncthreads();
    }

    float bbv[8];
    #pragma unroll
    for (int j = 0; j < 8; j++) {
        int col = n0 + tx*8 + j;
        bbv[j] = bias[col] + (bias2 ? bias2[col] : 0.f);
    }
    #pragma unroll
    for (int i = 0; i < 8; i++) {
        int row = m0 + ty*8 + i;
        if (row < M) {
            #pragma unroll
            for (int j = 0; j < 8; j++) {
                int col = n0 + tx*8 + j;
                float v = acc[i][j] + bbv[j];
                if (relu) v = fmaxf(v, 0.f);
                C[(size_t)row * N + col] = v;
            }
        }
    }
}

// ---------------- persistent LSTM: 128 CTAs, one grid barrier per step ----------------
__global__ __launch_bounds__(256) void lstm_kernel(const float* __restrict__ w_hh) {
    __shared__ float ws[8][264];        // [idx][(k>>5)*33 + (k&31)]
    __shared__ float gpart[32][8][9];   // [b][ks][idx]
    __shared__ float gfull[32][8];
    __shared__ float cstate[64];
    int cb = blockIdx.x;
    int tid = threadIdx.x;
    int j0 = cb * 2;

    for (int i = tid; i < 8 * 256; i += 256) {
        int idx = i >> 8, k = i & 255;
        int n = (idx >> 1) * 256 + j0 + (idx & 1);
        ws[idx][(k >> 5) * 33 + (k & 31)] = w_hh[(size_t)n * 256 + k];
    }
    if (tid < 64) cstate[tid] = 0.f;
    __syncthreads();

    int b = tid >> 3, ks = tid & 7;
    const unsigned nb = gridDim.x;

    for (int t = 0; t < SM1; t++) {
        float hreg[32];
        const float4* hp = reinterpret_cast<const float4*>(&d_hstate[t & 1][b*256 + ks*32]);
        #pragma unroll
        for (int i = 0; i < 8; i++) {
            float4 v = __ldcg(hp + i);
            hreg[4*i+0] = v.x; hreg[4*i+1] = v.y; hreg[4*i+2] = v.z; hreg[4*i+3] = v.w;
        }
        float acc[8] = {0.f,0.f,0.f,0.f,0.f,0.f,0.f,0.f};
        #pragma unroll
        for (int kk = 0; kk < 32; kk++) {
            float h = hreg[kk];
            #pragma unroll
            for (int idx = 0; idx < 8; idx++)
                acc[idx] = fmaf(h, ws[idx][ks*33 + kk], acc[idx]);
        }
        #pragma unroll
        for (int idx = 0; idx < 8; idx++) gpart[b][ks][idx] = acc[idx];
        __syncthreads();

        {   // reduce k-partials: thread (b, idx=ks)
            int idx = ks;
            float g = 0.f;
            #pragma unroll
            for (int s2 = 0; s2 < 8; s2++) g += gpart[b][s2][idx];
            int n = (idx >> 1) * 256 + j0 + (idx & 1);
            g += __ldg(&d_gx[((size_t)b*SM1 + t)*1024 + n]);
            gfull[b][idx] = g;
        }
        __syncthreads();

        if (tid < 64) {
            int bb2 = tid >> 1, j2 = tid & 1;
            float gi = gfull[bb2][0 + j2];
            float gf = gfull[bb2][2 + j2];
            float gg = gfull[bb2][4 + j2];
            float go = gfull[bb2][6 + j2];
            float cv = cstate[tid];
            float cn = sigmoidf_(gf) * cv + sigmoidf_(gi) * tanhf(gg);
            float hv = sigmoidf_(go) * tanhf(cn);
            cstate[tid] = cn;
            int hj = j0 + j2;
            __stcg(&d_hstate[(t + 1) & 1][bb2*256 + hj], hv);
            d_hall[((size_t)bb2*SM1 + t)*256 + hj] = hv;
        }

        // grid barrier
        __threadfence();
        __syncthreads();
        if (tid == 0) {
            unsigned gen = *(volatile unsigned*)&g_bar_gen;
            unsigned arr = atomicAdd(&g_bar_count, 1u);
            if (arr == nb - 1u) {
                atomicExch(&g_bar_count, 0u);
                __threadfence();
                atomicAdd(&g_bar_gen, 1u);
            } else {
                while (*(volatile unsigned*)&g_bar_gen == gen) { }
            }
        }
        __syncthreads();
    }
}

// ---------------- gathered output heads (one warp per m) ----------------
__device__ __forceinline__ float warp_sum(float v) {
    #pragma unroll
    for (int o = 16; o; o >>= 1) v += __shfl_xor_sync(0xffffffffu, v, o);
    return v;
}

__global__ __launch_bounds__(256) void gather_kernel(
    const int* __restrict__ qshft, const int* __restrict__ cshft,
    const float* __restrict__ qn_ow, const float* __restrict__ qn_ob,
    const float* __restrict__ cn_ow, const float* __restrict__ cn_ob,
    const float* __restrict__ qa_ow, const float* __restrict__ qa_ob,
    const float* __restrict__ ca_ow, const float* __restrict__ ca_ob,
    float* __restrict__ out)
{
    int m = blockIdx.x * 8 + (threadIdx.x >> 5);
    int lane = threadIdx.x & 31;

    // y_question_next
    float acc = 0.f;
    for (int k = lane; k < 768; k += 32)
        acc += d_hq[(size_t)m*768 + k] * qn_ow[k];
    float yqn = sigmoidf_(warp_sum(acc) + qn_ob[0]);

    // y_concept_next (avg over valid cshft)
    float ysum = 0.f; int cnt = 0;
    #pragma unroll
    for (int j = 0; j < MC; j++) {
        int cc = cshft[m*MC + j];
        if (cc >= 0) {
            float a = 0.f;
            for (int k = lane; k < 768; k += 32)
                a += d_hc[(size_t)m*768 + k] * cn_ow[(size_t)cc*768 + k];
            ysum += sigmoidf_(warp_sum(a) + cn_ob[cc]);
            cnt++;
        }
    }
    float ycn = ysum / (float)max(cnt, 1);

    // y_question_all
    int qi = qshft[m];
    float a2 = 0.f;
    for (int k = lane; k < 256; k += 32)
        a2 += d_hqa[(size_t)m*256 + k] * qa_ow[(size_t)qi*256 + k];
    float yqa = sigmoidf_(warp_sum(a2) + qa_ob[qi]);

    // y_concept_all
    float ysum2 = 0.f; int cnt2 = 0;
    #pragma unroll
    for (int j = 0; j < MC; j++) {
        int cc = cshft[m*MC + j];
        if (cc >= 0) {
            float a = 0.f;
            for (int k = lane; k < 256; k += 32)
                a += d_hca[(size_t)m*256 + k] * ca_ow[(size_t)cc*256 + k];
            ysum2 += sigmoidf_(warp_sum(a) + ca_ob[cc]);
            cnt2++;
        }
    }
    float yca = ysum2 / (float)max(cnt2, 1);

    if (lane == 0) {
        out[m]            = yqn;
        out[MTOT + m]     = ycn;
        out[2*MTOT + m]   = yqa;
        out[3*MTOT + m]   = yca;
    }
}

// ---------------- launch ----------------
extern "C" void kernel_launch(void* const* d_in, const int* in_sizes, int n_in,
                              void* d_out, int out_size) {
    const int*   q           = (const int*)d_in[0];
    const int*   c           = (const int*)d_in[1];
    const int*   r           = (const int*)d_in[2];
    const int*   qshft       = (const int*)d_in[3];
    const int*   cshft       = (const int*)d_in[4];
    const float* que_emb     = (const float*)d_in[5];
    const float* concept_emb = (const float*)d_in[6];
    const float* w_ih        = (const float*)d_in[7];
    const float* w_hh        = (const float*)d_in[8];
    const float* b_ih        = (const float*)d_in[9];
    const float* b_hh        = (const float*)d_in[10];
    const float* qn_lw = (const float*)d_in[11];
    const float* qn_lb = (const float*)d_in[12];
    const float* qn_ow = (const float*)d_in[13];
    const float* qn_ob = (const float*)d_in[14];
    const float* cn_lw = (const float*)d_in[15];
    const float* cn_lb = (const float*)d_in[16];
    const float* cn_ow = (const float*)d_in[17];
    const float* cn_ob = (const float*)d_in[18];
    const float* qa_lw = (const float*)d_in[19];
    const float* qa_lb = (const float*)d_in[20];
    const float* qa_ow = (const float*)d_in[21];
    const float* qa_ob = (const float*)d_in[22];
    const float* ca_lw = (const float*)d_in[23];
    const float* ca_lb = (const float*)d_in[24];
    const float* ca_ow = (const float*)d_in[25];
    const float* ca_ob = (const float*)d_in[26];
    float* out = (float*)d_out;

    float* p_qca;   cudaGetSymbolAddress((void**)&p_qca,   d_qca);
    float* p_gx;    cudaGetSymbolAddress((void**)&p_gx,    d_gx);
    float* p_hall;  cudaGetSymbolAddress((void**)&p_hall,  d_hall);
    float* p_hnext; cudaGetSymbolAddress((void**)&p_hnext, d_hnext);
    float* p_hq;    cudaGetSymbolAddress((void**)&p_hq,    d_hq);
    float* p_hc;    cudaGetSymbolAddress((void**)&p_hc,    d_hc);
    float* p_hqa;   cudaGetSymbolAddress((void**)&p_hqa,   d_hqa);
    float* p_hca;   cudaGetSymbolAddress((void**)&p_hca,   d_hca);

    init_kernel<<<1, 256>>>();
    embed_kernel<<<BB*SS, 256>>>(q, c, r, que_emb, concept_emb);

    // gx = qca @ w_ih^T + b_ih + b_hh
    {
        dim3 g(1024/128, (MTOT + 127)/128);
        sgemm_nt<<<g, 256>>>(p_qca, w_ih, b_ih, b_hh, p_gx, MTOT, 1024, 1024, 0);
    }
    lstm_kernel<<<128, 256>>>(w_hh);
    hnext_kernel<<<MTOT, 256>>>();

    {
        dim3 g(768/128, (MTOT + 127)/128);
        sgemm_nt<<<g, 256>>>(p_hnext, qn_lw, qn_lb, nullptr, p_hq, MTOT, 768, 768, 1);
        sgemm_nt<<<g, 256>>>(p_hnext, cn_lw, cn_lb, nullptr, p_hc, MTOT, 768, 768, 1);
    }
    {
        dim3 g(256/128, (MTOT + 127)/128);
        sgemm_nt<<<g, 256>>>(p_hall, qa_lw, qa_lb, nullptr, p_hqa, MTOT, 256, 256, 1);
        sgemm_nt<<<g, 256>>>(p_hall, ca_lw, ca_lb, nullptr, p_hca, MTOT, 256, 256, 1);
    }

    gather_kernel<<<MTOT/8, 256>>>(qshft, cshft, qn_ow, qn_ob, cn_ow, cn_ob,
                                   qa_ow, qa_ob, ca_ow, ca_ob, out);
    (void)in_sizes; (void)n_in; (void)out_size;
}

// round 3
// speedup vs baseline: 1.1571x; 1.1571x over previous
#include <cuda_runtime.h>
#include <math.h>
#include <stdint.h>

#define BB   32
#define SS   200
#define SM1  199
#define MTOT (BB*SM1)   // 6368
#define MC   4

typedef unsigned long long ull;

// ---------------- device-global scratch ----------------
__device__ float d_emb_qc[(size_t)BB*SS*512];
__device__ float d_qca[(size_t)MTOT*1024];
__device__ float d_gx[(size_t)MTOT*1024];
__device__ float d_hall[(size_t)MTOT*256];
__device__ float d_hnext[(size_t)MTOT*768];
__device__ float d_hq[(size_t)MTOT*768];
__device__ float d_hc[(size_t)MTOT*768];
__device__ float d_hqa[(size_t)MTOT*256];
__device__ float d_hca[(size_t)MTOT*256];

__device__ __forceinline__ float sigmoidf_(float x) { return 1.f / (1.f + expf(-x)); }

// f32x2 helpers
__device__ __forceinline__ void fma2(ull &acc, ull a, ull b) {
    asm("fma.rn.f32x2 %0, %1, %2, %0;" : "+l"(acc) : "l"(a), "l"(b));
}
__device__ __forceinline__ ull pk(float x, float y) {
    ull r; asm("mov.b64 %0, {%1,%2};" : "=l"(r) : "f"(x), "f"(y)); return r;
}
__device__ __forceinline__ float2 upk(ull v) {
    float2 r; asm("mov.b64 {%0,%1}, %2;" : "=f"(r.x), "=f"(r.y) : "l"(v)); return r;
}

__device__ __forceinline__ uint32_t smem_u32(const void* p) {
    uint32_t a;
    asm("{ .reg .u64 t; cvta.to.shared.u64 t, %1; cvt.u32.u64 %0, t; }" : "=r"(a) : "l"(p));
    return a;
}
__device__ __forceinline__ void st_cluster_f32(uint32_t saddr, uint32_t rank, float v) {
    uint32_t r;
    asm volatile("mapa.shared::cluster.u32 %0, %1, %2;" : "=r"(r) : "r"(saddr), "r"(rank));
    asm volatile("st.shared::cluster.f32 [%0], %1;" :: "r"(r), "f"(v) : "memory");
}
__device__ __forceinline__ void cluster_sync_() {
    asm volatile("barrier.cluster.arrive.aligned;" ::: "memory");
    asm volatile("barrier.cluster.wait.aligned;" ::: "memory");
}

// ---------------- embeddings + LSTM-input assembly ----------------
__global__ void embed_kernel(const int* __restrict__ q, const int* __restrict__ c,
                             const int* __restrict__ r,
                             const float* __restrict__ que_emb,
                             const float* __restrict__ concept_emb) {
    int bs = blockIdx.x;
    int b = bs / SS, s = bs % SS;
    int e = threadIdx.x;
    int qi = q[bs];
    float eq = que_emb[(size_t)qi*256 + e];
    float sum = 0.f; int cnt = 0;
    #pragma unroll
    for (int j = 0; j < MC; j++) {
        int cj = c[bs*MC + j];
        if (cj >= 0) { sum += concept_emb[(size_t)cj*256 + e]; cnt++; }
    }
    float ec = sum / (float)max(cnt, 1);
    size_t base = (size_t)bs * 512;
    d_emb_qc[base + e]       = eq;
    d_emb_qc[base + 256 + e] = ec;
    if (s < SM1) {
        float f1 = (float)r[bs];
        float f0 = 1.f - f1;
        size_t mb = ((size_t)b*SM1 + s) * 1024;
        d_qca[mb + e]       = eq * f0;
        d_qca[mb + 256 + e] = ec * f0;
        d_qca[mb + 512 + e] = eq * f1;
        d_qca[mb + 768 + e] = ec * f1;
    }
}

// ---------------- hnext = [emb_qc_shift | h] ----------------
__global__ void hnext_kernel() {
    int m = blockIdx.x;
    int b = m / SM1, t = m % SM1;
    int e = threadIdx.x;
    size_t src = ((size_t)b*SS + (t+1)) * 512;
    d_hnext[(size_t)m*768 + e]       = d_emb_qc[src + e];
    d_hnext[(size_t)m*768 + 256 + e] = d_emb_qc[src + 256 + e];
    d_hnext[(size_t)m*768 + 512 + e] = d_hall[(size_t)m*256 + e];
}

// ---------------- f32x2 NT SGEMM: C = A[M,K]*B[N,K]^T + bias (+bias2), opt ReLU
__global__ __launch_bounds__(256) void sgemm_nt(
    const float* __restrict__ A, const float* __restrict__ B,
    const float* __restrict__ bias, const float* __restrict__ bias2,
    float* __restrict__ C, int M, int N, int K, int relu)
{
    const int BM = 128, BN = 128, BK = 8;
    __shared__ __align__(16) float  As[BK][BM + 4];
    __shared__ __align__(16) float2 Bsd[BK*8*17];   // [(kk*8+j)*17 + tx], duplicated pairs
    int tid = threadIdx.x;
    int tx = tid & 15, ty = tid >> 4;
    int m0 = blockIdx.y * BM, n0 = blockIdx.x * BN;

    ull acc2[4][8];
    #pragma unroll
    for (int i = 0; i < 4; i++)
        #pragma unroll
        for (int j = 0; j < 8; j++) acc2[i][j] = 0ULL;

    int lrow = tid >> 1;
    int lkg  = (tid & 1) << 2;
    int jj   = lrow & 7;
    int txs  = lrow >> 3;

    for (int k0 = 0; k0 < K; k0 += BK) {
        float4 va = make_float4(0.f, 0.f, 0.f, 0.f);
        if (m0 + lrow < M)
            va = *reinterpret_cast<const float4*>(&A[(size_t)(m0 + lrow) * K + k0 + lkg]);
        As[lkg + 0][lrow] = va.x; As[lkg + 1][lrow] = va.y;
        As[lkg + 2][lrow] = va.z; As[lkg + 3][lrow] = va.w;

        float4 vb = *reinterpret_cast<const float4*>(&B[(size_t)(n0 + lrow) * K + k0 + lkg]);
        Bsd[((lkg + 0)*8 + jj)*17 + txs] = make_float2(vb.x, vb.x);
        Bsd[((lkg + 1)*8 + jj)*17 + txs] = make_float2(vb.y, vb.y);
        Bsd[((lkg + 2)*8 + jj)*17 + txs] = make_float2(vb.z, vb.z);
        Bsd[((lkg + 3)*8 + jj)*17 + txs] = make_float2(vb.w, vb.w);
        __syncthreads();

        #pragma unroll
        for (int kk = 0; kk < BK; kk++) {
            ulonglong2 aA = *reinterpret_cast<const ulonglong2*>(&As[kk][ty*8]);
            ulonglong2 aB = *reinterpret_cast<const ulonglong2*>(&As[kk][ty*8 + 4]);
            #pragma unroll
            for (int j = 0; j < 8; j++) {
                ull bd = *reinterpret_cast<const ull*>(&Bsd[(kk*8 + j)*17 + tx]);
                fma2(acc2[0][j], aA.x, bd);
                fma2(acc2[1][j], aA.y, bd);
                fma2(acc2[2][j], aB.x, bd);
                fma2(acc2[3][j], aB.y, bd);
            }
        }
        __syncthreads();
    }

    float bbv[8];
    #pragma unroll
    for (int j = 0; j < 8; j++) {
        int col = n0 + tx*8 + j;
        bbv[j] = bias[col] + (bias2 ? bias2[col] : 0.f);
    }
    #pragma unroll
    for (int i2 = 0; i2 < 4; i2++) {
        int row0 = m0 + ty*8 + 2*i2;
        #pragma unroll
        for (int j = 0; j < 8; j++) {
            float2 v = upk(acc2[i2][j]);
            int col = n0 + tx*8 + j;
            float v0 = v.x + bbv[j];
            float v1 = v.y + bbv[j];
            if (relu) { v0 = fmaxf(v0, 0.f); v1 = fmaxf(v1, 0.f); }
            if (row0 < M)     C[(size_t)row0 * N + col]     = v0;
            if (row0 + 1 < M) C[(size_t)(row0+1) * N + col] = v1;
        }
    }
}

// ---------------- cluster LSTM: 16 clusters x 8 CTAs, 2 batches/cluster ----------------
// CTA rank rk owns h-positions [rk*32, rk*32+32) -> 128 gate rows (i,f,g,o for those j).
// w_hh slice lives in registers. h broadcast to peers via DSMEM each step.
__global__ __cluster_dims__(8,1,1) __launch_bounds__(256, 1)
void lstm_kernel(const float* __restrict__ w_hh) {
    // SMEM: h double-buffered, swizzled (36-float stride per 32-k group)
    __shared__ __align__(16) float hbuf[2*2*288];   // [phase][batch][kg*36 + k%32]
    __shared__ float sgx[256];                       // [b*128 + lr]
    __shared__ float sgates[256];                    // [b*128 + lr]
    __shared__ float sc[64];                         // [b*32 + j]

    int tid = threadIdx.x;
    int rk  = blockIdx.x & 7;        // cluster rank
    int cl  = blockIdx.x >> 3;       // cluster id -> batches 2cl, 2cl+1

    int rb = tid >> 3;               // row-block 0..31 -> local rows 4rb..4rb+3
    int kg = tid & 7;                // k-group -> k in [kg*32, kg*32+32)

    // load w slice into registers: w2[r][p] = (w[k0+2p], w[k0+2p+1]), k0 = kg*32
    ull w2[4][16];
    #pragma unroll
    for (int r = 0; r < 4; r++) {
        int lr = 4*rb + r;
        int gr = ((lr >> 5) << 8) + rk*32 + (lr & 31);
        const float4* wp = reinterpret_cast<const float4*>(&w_hh[(size_t)gr*256 + kg*32]);
        #pragma unroll
        for (int i = 0; i < 8; i++) {
            float4 v = __ldg(wp + i);
            w2[r][2*i]   = pk(v.x, v.y);
            w2[r][2*i+1] = pk(v.z, v.w);
        }
    }

    // init state
    for (int i = tid; i < 2*2*288; i += 256) hbuf[i] = 0.f;
    if (tid < 64) sc[tid] = 0.f;
    __syncthreads();
    cluster_sync_();

    uint32_t hbase = smem_u32(hbuf);
    int pw_b = tid & 1;              // pointwise mapping (tid<64): j = tid>>1
    int pw_j = tid >> 1;
    int gx_b = tid & 1;              // gx prefetch mapping: lr = tid>>1
    int gx_lr = tid >> 1;
    int gx_gr = ((gx_lr >> 5) << 8) + rk*32 + (gx_lr & 31);
    size_t gx_base0 = ((size_t)(2*cl + gx_b) * SM1) * 1024 + gx_gr;

    for (int t = 0; t < SM1; t++) {
        // prefetch this step's x-gate contribution
        float gxv = __ldg(&d_gx[gx_base0 + (size_t)t * 1024]);

        int ph = t & 1;
        const float* h0p = &hbuf[(ph*2 + 0)*288 + kg*36];
        const float* h1p = &hbuf[(ph*2 + 1)*288 + kg*36];

        ull acc[4][2];
        #pragma unroll
        for (int r = 0; r < 4; r++) { acc[r][0] = 0ULL; acc[r][1] = 0ULL; }

        #pragma unroll
        for (int i = 0; i < 8; i++) {
            float4 h0 = *reinterpret_cast<const float4*>(h0p + 4*i);
            float4 h1 = *reinterpret_cast<const float4*>(h1p + 4*i);
            ull h0a = pk(h0.x, h0.y), h0b = pk(h0.z, h0.w);
            ull h1a = pk(h1.x, h1.y), h1b = pk(h1.z, h1.w);
            #pragma unroll
            for (int r = 0; r < 4; r++) {
                fma2(acc[r][0], w2[r][2*i],   h0a);
                fma2(acc[r][0], w2[r][2*i+1], h0b);
                fma2(acc[r][1], w2[r][2*i],   h1a);
                fma2(acc[r][1], w2[r][2*i+1], h1b);
            }
        }

        sgx[gx_b*128 + gx_lr] = gxv;

        // horizontal + reduce over 8 k-groups (lanes)
        float s[4][2];
        #pragma unroll
        for (int r = 0; r < 4; r++) {
            float2 a0 = upk(acc[r][0]); s[r][0] = a0.x + a0.y;
            float2 a1 = upk(acc[r][1]); s[r][1] = a1.x + a1.y;
        }
        #pragma unroll
        for (int d = 4; d; d >>= 1) {
            #pragma unroll
            for (int r = 0; r < 4; r++) {
                s[r][0] += __shfl_down_sync(0xffffffffu, s[r][0], d, 8);
                s[r][1] += __shfl_down_sync(0xffffffffu, s[r][1], d, 8);
            }
        }
        __syncthreads();   // sgx visible
        if (kg == 0) {
            #pragma unroll
            for (int r = 0; r < 4; r++) {
                int lr = 4*rb + r;
                sgates[0*128 + lr] = s[r][0] + sgx[0*128 + lr];
                sgates[1*128 + lr] = s[r][1] + sgx[1*128 + lr];
            }
        }
        __syncthreads();   // sgates visible

        if (tid < 64) {
            int b = pw_b, j = pw_j;
            float gi = sgates[b*128 + j];
            float gf = sgates[b*128 + 32 + j];
            float gg = sgates[b*128 + 64 + j];
            float go = sgates[b*128 + 96 + j];
            float cv = sc[b*32 + j];
            float cn = sigmoidf_(gf) * cv + sigmoidf_(gi) * tanhf(gg);
            float hv = sigmoidf_(go) * tanhf(cn);
            sc[b*32 + j] = cn;
            d_hall[((size_t)(2*cl + b)*SM1 + t)*256 + rk*32 + j] = hv;
            // broadcast new h to all 8 cluster CTAs (next phase buffer)
            uint32_t off = hbase + (uint32_t)((((t+1)&1)*2 + b)*288 + rk*36 + j) * 4u;
            #pragma unroll
            for (int dst = 0; dst < 8; dst++)
                st_cluster_f32(off, (uint32_t)dst, hv);
        }
        cluster_sync_();
    }
}

// ---------------- gathered output heads ----------------
__device__ __forceinline__ float warp_sum(float v) {
    #pragma unroll
    for (int o = 16; o; o >>= 1) v += __shfl_xor_sync(0xffffffffu, v, o);
    return v;
}

__global__ __launch_bounds__(256) void gather_kernel(
    const int* __restrict__ qshft, const int* __restrict__ cshft,
    const float* __restrict__ qn_ow, const float* __restrict__ qn_ob,
    const float* __restrict__ cn_ow, const float* __restrict__ cn_ob,
    const float* __restrict__ qa_ow, const float* __restrict__ qa_ob,
    const float* __restrict__ ca_ow, const float* __restrict__ ca_ob,
    float* __restrict__ out)
{
    int m = blockIdx.x * 8 + (threadIdx.x >> 5);
    int lane = threadIdx.x & 31;

    float acc = 0.f;
    for (int k = lane; k < 768; k += 32)
        acc += d_hq[(size_t)m*768 + k] * qn_ow[k];
    float yqn = sigmoidf_(warp_sum(acc) + qn_ob[0]);

    float ysum = 0.f; int cnt = 0;
    #pragma unroll
    for (int j = 0; j < MC; j++) {
        int cc = cshft[m*MC + j];
        if (cc >= 0) {
            float a = 0.f;
            for (int k = lane; k < 768; k += 32)
                a += d_hc[(size_t)m*768 + k] * cn_ow[(size_t)cc*768 + k];
            ysum += sigmoidf_(warp_sum(a) + cn_ob[cc]);
            cnt++;
        }
    }
    float ycn = ysum / (float)max(cnt, 1);

    int qi = qshft[m];
    float a2 = 0.f;
    for (int k = lane; k < 256; k += 32)
        a2 += d_hqa[(size_t)m*256 + k] * qa_ow[(size_t)qi*256 + k];
    float yqa = sigmoidf_(warp_sum(a2) + qa_ob[qi]);

    float ysum2 = 0.f; int cnt2 = 0;
    #pragma unroll
    for (int j = 0; j < MC; j++) {
        int cc = cshft[m*MC + j];
        if (cc >= 0) {
            float a = 0.f;
            for (int k = lane; k < 256; k += 32)
                a += d_hca[(size_t)m*256 + k] * ca_ow[(size_t)cc*256 + k];
            ysum2 += sigmoidf_(warp_sum(a) + ca_ob[cc]);
            cnt2++;
        }
    }
    float yca = ysum2 / (float)max(cnt2, 1);

    if (lane == 0) {
        out[m]            = yqn;
        out[MTOT + m]     = ycn;
        out[2*MTOT + m]   = yqa;
        out[3*MTOT + m]   = yca;
    }
}

// ---------------- launch ----------------
extern "C" void kernel_launch(void* const* d_in, const int* in_sizes, int n_in,
                              void* d_out, int out_size) {
    const int*   q           = (const int*)d_in[0];
    const int*   c           = (const int*)d_in[1];
    const int*   r           = (const int*)d_in[2];
    const int*   qshft       = (const int*)d_in[3];
    const int*   cshft       = (const int*)d_in[4];
    const float* que_emb     = (const float*)d_in[5];
    const float* concept_emb = (const float*)d_in[6];
    const float* w_ih        = (const float*)d_in[7];
    const float* w_hh        = (const float*)d_in[8];
    const float* b_ih        = (const float*)d_in[9];
    const float* b_hh        = (const float*)d_in[10];
    const float* qn_lw = (const float*)d_in[11];
    const float* qn_lb = (const float*)d_in[12];
    const float* qn_ow = (const float*)d_in[13];
    const float* qn_ob = (const float*)d_in[14];
    const float* cn_lw = (const float*)d_in[15];
    const float* cn_lb = (const float*)d_in[16];
    const float* cn_ow = (const float*)d_in[17];
    const float* cn_ob = (const float*)d_in[18];
    const float* qa_lw = (const float*)d_in[19];
    const float* qa_lb = (const float*)d_in[20];
    const float* qa_ow = (const float*)d_in[21];
    const float* qa_ob = (const float*)d_in[22];
    const float* ca_lw = (const float*)d_in[23];
    const float* ca_lb = (const float*)d_in[24];
    const float* ca_ow = (const float*)d_in[25];
    const float* ca_ob = (const float*)d_in[26];
    float* out = (float*)d_out;

    float* p_qca;   cudaGetSymbolAddress((void**)&p_qca,   d_qca);
    float* p_gx;    cudaGetSymbolAddress((void**)&p_gx,    d_gx);
    float* p_hall;  cudaGetSymbolAddress((void**)&p_hall,  d_hall);
    float* p_hnext; cudaGetSymbolAddress((void**)&p_hnext, d_hnext);
    float* p_hq;    cudaGetSymbolAddress((void**)&p_hq,    d_hq);
    float* p_hc;    cudaGetSymbolAddress((void**)&p_hc,    d_hc);
    float* p_hqa;   cudaGetSymbolAddress((void**)&p_hqa,   d_hqa);
    float* p_hca;   cudaGetSymbolAddress((void**)&p_hca,   d_hca);

    embed_kernel<<<BB*SS, 256>>>(q, c, r, que_emb, concept_emb);

    {   // gx = qca @ w_ih^T + b_ih + b_hh
        dim3 g(1024/128, (MTOT + 127)/128);
        sgemm_nt<<<g, 256>>>(p_qca, w_ih, b_ih, b_hh, p_gx, MTOT, 1024, 1024, 0);
    }
    lstm_kernel<<<128, 256>>>(w_hh);
    hnext_kernel<<<MTOT, 256>>>();

    {
        dim3 g(768/128, (MTOT + 127)/128);
        sgemm_nt<<<g, 256>>>(p_hnext, qn_lw, qn_lb, nullptr, p_hq, MTOT, 768, 768, 1);
        sgemm_nt<<<g, 256>>>(p_hnext, cn_lw, cn_lb, nullptr, p_hc, MTOT, 768, 768, 1);
    }
    {
        dim3 g(256/128, (MTOT + 127)/128);
        sgemm_nt<<<g, 256>>>(p_hall, qa_lw, qa_lb, nullptr, p_hqa, MTOT, 256, 256, 1);
        sgemm_nt<<<g, 256>>>(p_hall, ca_lw, ca_lb, nullptr, p_hca, MTOT, 256, 256, 1);
    }

    gather_kernel<<<MTOT/8, 256>>>(qshft, cshft, qn_ow, qn_ob, cn_ow, cn_ob,
                                   qa_ow, qa_ob, ca_ow, ca_ob, out);
    (void)in_sizes; (void)n_in; (void)out_size;
}

// round 5
// speedup vs baseline: 1.7792x; 1.5376x over previous
#include <cuda_runtime.h>
#include <cuda_bf16.h>
#include <mma.h>
#include <math.h>
#include <stdint.h>

using namespace nvcuda;

#define BB   32
#define SS   200
#define SM1  199
#define MTOT (BB*SM1)   // 6368
#define MPAD 6400       // 50 * 128
#define MC   4

typedef unsigned long long ull;

// ---------------- device-global scratch ----------------
__device__ float d_emb_qc[(size_t)BB*SS*512];
__device__ float d_gx[(size_t)MTOT*1024];
__device__ float d_hall[(size_t)MTOT*256];
__device__ float d_hq[(size_t)MTOT*768];
__device__ float d_hc[(size_t)MTOT*768];
__device__ float d_hqa[(size_t)MTOT*256];
__device__ float d_hca[(size_t)MTOT*256];

// bf16 hi/lo split operands (pad rows stay zero)
__device__ __nv_bfloat16 g_qca_hi[(size_t)MPAD*1024];
__device__ __nv_bfloat16 g_qca_lo[(size_t)MPAD*1024];
__device__ __nv_bfloat16 g_wih_hi[1024*1024];
__device__ __nv_bfloat16 g_wih_lo[1024*1024];
__device__ __nv_bfloat16 g_hnx_hi[(size_t)MPAD*768];
__device__ __nv_bfloat16 g_hnx_lo[(size_t)MPAD*768];
__device__ __nv_bfloat16 g_hal_hi[(size_t)MPAD*256];
__device__ __nv_bfloat16 g_hal_lo[(size_t)MPAD*256];
__device__ __nv_bfloat16 g_wqn_hi[768*768];
__device__ __nv_bfloat16 g_wqn_lo[768*768];
__device__ __nv_bfloat16 g_wcn_hi[768*768];
__device__ __nv_bfloat16 g_wcn_lo[768*768];
__device__ __nv_bfloat16 g_wqa_hi[256*256];
__device__ __nv_bfloat16 g_wqa_lo[256*256];
__device__ __nv_bfloat16 g_wca_hi[256*256];
__device__ __nv_bfloat16 g_wca_lo[256*256];

__device__ __forceinline__ float sigmoidf_(float x) { return 1.f / (1.f + expf(-x)); }

__device__ __forceinline__ void wsplit(__nv_bfloat16* hi, __nv_bfloat16* lo, size_t i, float v) {
    __nv_bfloat16 h = __float2bfloat16_rn(v);
    hi[i] = h;
    lo[i] = __float2bfloat16_rn(v - __bfloat162float(h));
}

// f32x2 helpers (LSTM)
__device__ __forceinline__ void fma2(ull &acc, ull a, ull b) {
    asm("fma.rn.f32x2 %0, %1, %2, %0;" : "+l"(acc) : "l"(a), "l"(b));
}
__device__ __forceinline__ ull pk(float x, float y) {
    ull r; asm("mov.b64 %0, {%1,%2};" : "=l"(r) : "f"(x), "f"(y)); return r;
}
__device__ __forceinline__ float2 upk(ull v) {
    float2 r; asm("mov.b64 {%0,%1}, %2;" : "=f"(r.x), "=f"(r.y) : "l"(v)); return r;
}
__device__ __forceinline__ uint32_t smem_u32(const void* p) {
    uint32_t a;
    asm("{ .reg .u64 t; cvta.to.shared.u64 t, %1; cvt.u32.u64 %0, t; }" : "=r"(a) : "l"(p));
    return a;
}
__device__ __forceinline__ void st_cluster_f32(uint32_t saddr, uint32_t rank, float v) {
    uint32_t r;
    asm volatile("mapa.shared::cluster.u32 %0, %1, %2;" : "=r"(r) : "r"(saddr), "r"(rank));
    asm volatile("st.shared::cluster.f32 [%0], %1;" :: "r"(r), "f"(v) : "memory");
}
__device__ __forceinline__ void cluster_sync_() {
    asm volatile("barrier.cluster.arrive.aligned;" ::: "memory");
    asm volatile("barrier.cluster.wait.aligned;" ::: "memory");
}

// ---------------- embeddings + LSTM-input assembly ----------------
__global__ void embed_kernel(const int* __restrict__ q, const int* __restrict__ c,
                             const int* __restrict__ r,
                             const float* __restrict__ que_emb,
                             const float* __restrict__ concept_emb) {
    int bs = blockIdx.x;
    int b = bs / SS, s = bs % SS;
    int e = threadIdx.x;
    int qi = q[bs];
    float eq = que_emb[(size_t)qi*256 + e];
    float sum = 0.f; int cnt = 0;
    #pragma unroll
    for (int j = 0; j < MC; j++) {
        int cj = c[bs*MC + j];
        if (cj >= 0) { sum += concept_emb[(size_t)cj*256 + e]; cnt++; }
    }
    float ec = sum / (float)max(cnt, 1);
    size_t base = (size_t)bs * 512;
    d_emb_qc[base + e]       = eq;
    d_emb_qc[base + 256 + e] = ec;
    if (s < SM1) {
        float f1 = (float)r[bs];
        float f0 = 1.f - f1;
        size_t mb = ((size_t)b*SM1 + s) * 1024;
        wsplit(g_qca_hi, g_qca_lo, mb + e,       eq * f0);
        wsplit(g_qca_hi, g_qca_lo, mb + 256 + e, ec * f0);
        wsplit(g_qca_hi, g_qca_lo, mb + 512 + e, eq * f1);
        wsplit(g_qca_hi, g_qca_lo, mb + 768 + e, ec * f1);
    }
}

// ---------------- hnext (bf16 split) ----------------
__global__ void hnext_kernel() {
    int m = blockIdx.x;
    int b = m / SM1, t = m % SM1;
    int e = threadIdx.x;
    size_t src = ((size_t)b*SS + (t+1)) * 512;
    wsplit(g_hnx_hi, g_hnx_lo, (size_t)m*768 + e,       d_emb_qc[src + e]);
    wsplit(g_hnx_hi, g_hnx_lo, (size_t)m*768 + 256 + e, d_emb_qc[src + 256 + e]);
    wsplit(g_hnx_hi, g_hnx_lo, (size_t)m*768 + 512 + e, d_hall[(size_t)m*256 + e]);
}

// ---------------- f32 -> bf16 hi/lo split converter ----------------
__global__ void cvt_split(const float* __restrict__ s, __nv_bfloat16* __restrict__ hi,
                          __nv_bfloat16* __restrict__ lo, int n) {
    int i = (blockIdx.x * 256 + threadIdx.x) * 4;
    if (i >= n) return;
    float4 v = *reinterpret_cast<const float4*>(s + i);
    __nv_bfloat16 h0 = __float2bfloat16_rn(v.x), h1 = __float2bfloat16_rn(v.y);
    __nv_bfloat16 h2 = __float2bfloat16_rn(v.z), h3 = __float2bfloat16_rn(v.w);
    __nv_bfloat16 l0 = __float2bfloat16_rn(v.x - __bfloat162float(h0));
    __nv_bfloat16 l1 = __float2bfloat16_rn(v.y - __bfloat162float(h1));
    __nv_bfloat16 l2 = __float2bfloat16_rn(v.z - __bfloat162float(h2));
    __nv_bfloat16 l3 = __float2bfloat16_rn(v.w - __bfloat162float(h3));
    reinterpret_cast<__nv_bfloat162*>(hi + i)[0] = __halves2bfloat162(h0, h1);
    reinterpret_cast<__nv_bfloat162*>(hi + i)[1] = __halves2bfloat162(h2, h3);
    reinterpret_cast<__nv_bfloat162*>(lo + i)[0] = __halves2bfloat162(l0, l1);
    reinterpret_cast<__nv_bfloat162*>(lo + i)[1] = __halves2bfloat162(l2, l3);
}

// ---------------- wmma bf16-split GEMM ----------------
// C[M,N] = A[M,K]*B[N,K]^T + bias (+bias2), opt ReLU.  hi/lo bf16 operands.
// Tile 128x128, BK=32, 8 warps (4x2), warp tile 32x64, fp32 accum.
#define GEMM_SMEM 40960
__global__ __launch_bounds__(256) void mma_gemm(
    const __nv_bfloat16* __restrict__ Ahi, const __nv_bfloat16* __restrict__ Alo,
    const __nv_bfloat16* __restrict__ Bhi, const __nv_bfloat16* __restrict__ Blo,
    const float* __restrict__ bias, const float* __restrict__ bias2,
    float* __restrict__ C, int M, int N, int K, int relu)
{
    extern __shared__ __align__(16) char smem[];
    __shared__ float sbias[128];
    __nv_bfloat16* tile[4];
    tile[0] = reinterpret_cast<__nv_bfloat16*>(smem);            // Ahi 128x40
    tile[1] = tile[0] + 5120;                                    // Alo
    tile[2] = tile[1] + 5120;                                    // Bhi
    tile[3] = tile[2] + 5120;                                    // Blo

    int tid = threadIdx.x;
    int w = tid >> 5, lane = tid & 31;
    int wm = w >> 1, wn = w & 1;
    int m0 = blockIdx.y * 128, n0 = blockIdx.x * 128;

    if (tid < 128) sbias[tid] = bias[n0 + tid] + (bias2 ? bias2[n0 + tid] : 0.f);

    wmma::fragment<wmma::accumulator, 16, 16, 16, float> acc[2][4];
    #pragma unroll
    for (int i = 0; i < 2; i++)
        #pragma unroll
        for (int j = 0; j < 4; j++) wmma::fill_fragment(acc[i][j], 0.f);

    const __nv_bfloat16* mats[4] = {Ahi, Alo, Bhi, Blo};
    const int r0s[4] = {m0, m0, n0, n0};

    for (int k0 = 0; k0 < K; k0 += 32) {
        #pragma unroll
        for (int mt = 0; mt < 4; mt++) {
            #pragma unroll
            for (int i = 0; i < 2; i++) {
                int o = i * 256 + tid;
                int row = o >> 2, c8 = (o & 3) * 8;
                *reinterpret_cast<float4*>(tile[mt] + row * 40 + c8) =
                    *reinterpret_cast<const float4*>(mats[mt] + (size_t)(r0s[mt] + row) * K + k0 + c8);
            }
        }
        __syncthreads();

        #pragma unroll
        for (int ks = 0; ks < 32; ks += 16) {
            wmma::fragment<wmma::matrix_a, 16, 16, 16, __nv_bfloat16, wmma::row_major> ah[2], al[2];
            #pragma unroll
            for (int i = 0; i < 2; i++) {
                wmma::load_matrix_sync(ah[i], tile[0] + (wm*32 + i*16) * 40 + ks, 40);
                wmma::load_matrix_sync(al[i], tile[1] + (wm*32 + i*16) * 40 + ks, 40);
            }
            #pragma unroll
            for (int j = 0; j < 4; j++) {
                wmma::fragment<wmma::matrix_b, 16, 16, 16, __nv_bfloat16, wmma::col_major> bh, bl;
                wmma::load_matrix_sync(bh, tile[2] + (wn*64 + j*16) * 40 + ks, 40);
                wmma::load_matrix_sync(bl, tile[3] + (wn*64 + j*16) * 40 + ks, 40);
                #pragma unroll
                for (int i = 0; i < 2; i++) {
                    wmma::mma_sync(acc[i][j], ah[i], bh, acc[i][j]);
                    wmma::mma_sync(acc[i][j], ah[i], bl, acc[i][j]);
                    wmma::mma_sync(acc[i][j], al[i], bh, acc[i][j]);
                }
            }
        }
        __syncthreads();
    }

    // epilogue: per-warp 16x20 f32 stage (aliases tiles; tiles dead now)
    float* stage = reinterpret_cast<float*>(smem) + w * 320;
    int r = lane >> 1, c0 = (lane & 1) * 8;
    #pragma unroll
    for (int i = 0; i < 2; i++) {
        #pragma unroll
        for (int j = 0; j < 4; j++) {
            wmma::store_matrix_sync(stage, acc[i][j], 20, wmma::mem_row_major);
            __syncwarp();
            int gm = m0 + wm*32 + i*16 + r;
            if (gm < M) {
                int nc = wn*64 + j*16 + c0;
                float4 v0, v1;
                v0.x = stage[r*20 + c0 + 0] + sbias[nc + 0];
                v0.y = stage[r*20 + c0 + 1] + sbias[nc + 1];
                v0.z = stage[r*20 + c0 + 2] + sbias[nc + 2];
                v0.w = stage[r*20 + c0 + 3] + sbias[nc + 3];
                v1.x = stage[r*20 + c0 + 4] + sbias[nc + 4];
                v1.y = stage[r*20 + c0 + 5] + sbias[nc + 5];
                v1.z = stage[r*20 + c0 + 6] + sbias[nc + 6];
                v1.w = stage[r*20 + c0 + 7] + sbias[nc + 7];
                if (relu) {
                    v0.x = fmaxf(v0.x, 0.f); v0.y = fmaxf(v0.y, 0.f);
                    v0.z = fmaxf(v0.z, 0.f); v0.w = fmaxf(v0.w, 0.f);
                    v1.x = fmaxf(v1.x, 0.f); v1.y = fmaxf(v1.y, 0.f);
                    v1.z = fmaxf(v1.z, 0.f); v1.w = fmaxf(v1.w, 0.f);
                }
                *reinterpret_cast<float4*>(&C[(size_t)gm * N + n0 + nc])     = v0;
                *reinterpret_cast<float4*>(&C[(size_t)gm * N + n0 + nc + 4]) = v1;
            }
            __syncwarp();
        }
    }
}

// ---------------- cluster LSTM ----------------
__global__ __cluster_dims__(8,1,1) __launch_bounds__(256, 1)
void lstm_kernel(const float* __restrict__ w_hh) {
    __shared__ __align__(16) float hbuf[2*2*288];
    __shared__ float sgx[256];
    __shared__ float sgates[256];
    __shared__ float sc[64];

    int tid = threadIdx.x;
    int rk  = blockIdx.x & 7;
    int cl  = blockIdx.x >> 3;

    int rb = tid >> 3;
    int kg = tid & 7;

    ull w2[4][16];
    #pragma unroll
    for (int r = 0; r < 4; r++) {
        int lr = 4*rb + r;
        int gr = ((lr >> 5) << 8) + rk*32 + (lr & 31);
        const float4* wp = reinterpret_cast<const float4*>(&w_hh[(size_t)gr*256 + kg*32]);
        #pragma unroll
        for (int i = 0; i < 8; i++) {
            float4 v = __ldg(wp + i);
            w2[r][2*i]   = pk(v.x, v.y);
            w2[r][2*i+1] = pk(v.z, v.w);
        }
    }

    for (int i = tid; i < 2*2*288; i += 256) hbuf[i] = 0.f;
    if (tid < 64) sc[tid] = 0.f;
    __syncthreads();
    cluster_sync_();

    uint32_t hbase = smem_u32(hbuf);
    int pw_b = tid & 1;
    int pw_j = tid >> 1;
    int gx_b = tid & 1;
    int gx_lr = tid >> 1;
    int gx_gr = ((gx_lr >> 5) << 8) + rk*32 + (gx_lr & 31);
    size_t gx_base0 = ((size_t)(2*cl + gx_b) * SM1) * 1024 + gx_gr;

    for (int t = 0; t < SM1; t++) {
        float gxv = __ldg(&d_gx[gx_base0 + (size_t)t * 1024]);

        int ph = t & 1;
        const float* h0p = &hbuf[(ph*2 + 0)*288 + kg*36];
        const float* h1p = &hbuf[(ph*2 + 1)*288 + kg*36];

        ull acc[4][2];
        #pragma unroll
        for (int r = 0; r < 4; r++) { acc[r][0] = 0ULL; acc[r][1] = 0ULL; }

        #pragma unroll
        for (int i = 0; i < 8; i++) {
            float4 h0 = *reinterpret_cast<const float4*>(h0p + 4*i);
            float4 h1 = *reinterpret_cast<const float4*>(h1p + 4*i);
            ull h0a = pk(h0.x, h0.y), h0b = pk(h0.z, h0.w);
            ull h1a = pk(h1.x, h1.y), h1b = pk(h1.z, h1.w);
            #pragma unroll
            for (int r = 0; r < 4; r++) {
                fma2(acc[r][0], w2[r][2*i],   h0a);
                fma2(acc[r][0], w2[r][2*i+1], h0b);
                fma2(acc[r][1], w2[r][2*i],   h1a);
                fma2(acc[r][1], w2[r][2*i+1], h1b);
            }
        }

        sgx[gx_b*128 + gx_lr] = gxv;

        float s[4][2];
        #pragma unroll
        for (int r = 0; r < 4; r++) {
            float2 a0 = upk(acc[r][0]); s[r][0] = a0.x + a0.y;
            float2 a1 = upk(acc[r][1]); s[r][1] = a1.x + a1.y;
        }
        #pragma unroll
        for (int d = 4; d; d >>= 1) {
            #pragma unroll
            for (int r = 0; r < 4; r++) {
                s[r][0] += __shfl_down_sync(0xffffffffu, s[r][0], d, 8);
                s[r][1] += __shfl_down_sync(0xffffffffu, s[r][1], d, 8);
            }
        }
        __syncthreads();
        if (kg == 0) {
            #pragma unroll
            for (int r = 0; r < 4; r++) {
                int lr = 4*rb + r;
                sgates[0*128 + lr] = s[r][0] + sgx[0*128 + lr];
                sgates[1*128 + lr] = s[r][1] + sgx[1*128 + lr];
            }
        }
        __syncthreads();

        if (tid < 64) {
            int b = pw_b, j = pw_j;
            float gi = sgates[b*128 + j];
            float gf = sgates[b*128 + 32 + j];
            float gg = sgates[b*128 + 64 + j];
            float go = sgates[b*128 + 96 + j];
            float cv = sc[b*32 + j];
            float cn = sigmoidf_(gf) * cv + sigmoidf_(gi) * tanhf(gg);
            float hv = sigmoidf_(go) * tanhf(cn);
            sc[b*32 + j] = cn;
            size_t hrow = ((size_t)(2*cl + b)*SM1 + t)*256 + rk*32 + j;
            d_hall[hrow] = hv;
            __nv_bfloat16 hh = __float2bfloat16_rn(hv);
            g_hal_hi[hrow] = hh;
            g_hal_lo[hrow] = __float2bfloat16_rn(hv - __bfloat162float(hh));
            uint32_t off = hbase + (uint32_t)((((t+1)&1)*2 + b)*288 + rk*36 + j) * 4u;
            #pragma unroll
            for (int dst = 0; dst < 8; dst++)
                st_cluster_f32(off, (uint32_t)dst, hv);
        }
        cluster_sync_();
    }
}

// ---------------- gathered output heads ----------------
__device__ __forceinline__ float warp_sum(float v) {
    #pragma unroll
    for (int o = 16; o; o >>= 1) v += __shfl_xor_sync(0xffffffffu, v, o);
    return v;
}

__global__ __launch_bounds__(256) void gather_kernel(
    const int* __restrict__ qshft, const int* __restrict__ cshft,
    const float* __restrict__ qn_ow, const float* __restrict__ qn_ob,
    const float* __restrict__ cn_ow, const float* __restrict__ cn_ob,
    const float* __restrict__ qa_ow, const float* __restrict__ qa_ob,
    const float* __restrict__ ca_ow, const float* __restrict__ ca_ob,
    float* __restrict__ out)
{
    int m = blockIdx.x * 8 + (threadIdx.x >> 5);
    int lane = threadIdx.x & 31;

    float acc = 0.f;
    for (int k = lane; k < 768; k += 32)
        acc += d_hq[(size_t)m*768 + k] * qn_ow[k];
    float yqn = sigmoidf_(warp_sum(acc) + qn_ob[0]);

    float ysum = 0.f; int cnt = 0;
    #pragma unroll
    for (int j = 0; j < MC; j++) {
        int cc = cshft[m*MC + j];
        if (cc >= 0) {
            float a = 0.f;
            for (int k = lane; k < 768; k += 32)
                a += d_hc[(size_t)m*768 + k] * cn_ow[(size_t)cc*768 + k];
            ysum += sigmoidf_(warp_sum(a) + cn_ob[cc]);
            cnt++;
        }
    }
    float ycn = ysum / (float)max(cnt, 1);

    int qi = qshft[m];
    float a2 = 0.f;
    for (int k = lane; k < 256; k += 32)
        a2 += d_hqa[(size_t)m*256 + k] * qa_ow[(size_t)qi*256 + k];
    float yqa = sigmoidf_(warp_sum(a2) + qa_ob[qi]);

    float ysum2 = 0.f; int cnt2 = 0;
    #pragma unroll
    for (int j = 0; j < MC; j++) {
        int cc = cshft[m*MC + j];
        if (cc >= 0) {
            float a = 0.f;
            for (int k = lane; k < 256; k += 32)
                a += d_hca[(size_t)m*256 + k] * ca_ow[(size_t)cc*256 + k];
            ysum2 += sigmoidf_(warp_sum(a) + ca_ob[cc]);
            cnt2++;
        }
    }
    float yca = ysum2 / (float)max(cnt2, 1);

    if (lane == 0) {
        out[m]            = yqn;
        out[MTOT + m]     = ycn;
        out[2*MTOT + m]   = yqa;
        out[3*MTOT + m]   = yca;
    }
}

// ---------------- launch ----------------
extern "C" void kernel_launch(void* const* d_in, const int* in_sizes, int n_in,
                              void* d_out, int out_size) {
    const int*   q           = (const int*)d_in[0];
    const int*   c           = (const int*)d_in[1];
    const int*   r           = (const int*)d_in[2];
    const int*   qshft       = (const int*)d_in[3];
    const int*   cshft       = (const int*)d_in[4];
    const float* que_emb     = (const float*)d_in[5];
    const float* concept_emb = (const float*)d_in[6];
    const float* w_ih        = (const float*)d_in[7];
    const float* w_hh        = (const float*)d_in[8];
    const float* b_ih        = (const float*)d_in[9];
    const float* b_hh        = (const float*)d_in[10];
    const float* qn_lw = (const float*)d_in[11];
    const float* qn_lb = (const float*)d_in[12];
    const float* qn_ow = (const float*)d_in[13];
    const float* qn_ob = (const float*)d_in[14];
    const float* cn_lw = (const float*)d_in[15];
    const float* cn_lb = (const float*)d_in[16];
    const float* cn_ow = (const float*)d_in[17];
    const float* cn_ob = (const float*)d_in[18];
    const float* qa_lw = (const float*)d_in[19];
    const float* qa_lb = (const float*)d_in[20];
    const float* qa_ow = (const float*)d_in[21];
    const float* qa_ob = (const float*)d_in[22];
    const float* ca_lw = (const float*)d_in[23];
    const float* ca_lb = (const float*)d_in[24];
    const float* ca_ow = (const float*)d_in[25];
    const float* ca_ob = (const float*)d_in[26];
    float* out = (float*)d_out;

    float* p_gx;  cudaGetSymbolAddress((void**)&p_gx,  d_gx);
    float* p_hq;  cudaGetSymbolAddress((void**)&p_hq,  d_hq);
    float* p_hc;  cudaGetSymbolAddress((void**)&p_hc,  d_hc);
    float* p_hqa; cudaGetSymbolAddress((void**)&p_hqa, d_hqa);
    float* p_hca; cudaGetSymbolAddress((void**)&p_hca, d_hca);
    __nv_bfloat16 *p_qca_hi, *p_qca_lo, *p_wih_hi, *p_wih_lo;
    __nv_bfloat16 *p_hnx_hi, *p_hnx_lo, *p_hal_hi, *p_hal_lo;
    __nv_bfloat16 *p_wqn_hi, *p_wqn_lo, *p_wcn_hi, *p_wcn_lo;
    __nv_bfloat16 *p_wqa_hi, *p_wqa_lo, *p_wca_hi, *p_wca_lo;
    cudaGetSymbolAddress((void**)&p_qca_hi, g_qca_hi);
    cudaGetSymbolAddress((void**)&p_qca_lo, g_qca_lo);
    cudaGetSymbolAddress((void**)&p_wih_hi, g_wih_hi);
    cudaGetSymbolAddress((void**)&p_wih_lo, g_wih_lo);
    cudaGetSymbolAddress((void**)&p_hnx_hi, g_hnx_hi);
    cudaGetSymbolAddress((void**)&p_hnx_lo, g_hnx_lo);
    cudaGetSymbolAddress((void**)&p_hal_hi, g_hal_hi);
    cudaGetSymbolAddress((void**)&p_hal_lo, g_hal_lo);
    cudaGetSymbolAddress((void**)&p_wqn_hi, g_wqn_hi);
    cudaGetSymbolAddress((void**)&p_wqn_lo, g_wqn_lo);
    cudaGetSymbolAddress((void**)&p_wcn_hi, g_wcn_hi);
    cudaGetSymbolAddress((void**)&p_wcn_lo, g_wcn_lo);
    cudaGetSymbolAddress((void**)&p_wqa_hi, g_wqa_hi);
    cudaGetSymbolAddress((void**)&p_wqa_lo, g_wqa_lo);
    cudaGetSymbolAddress((void**)&p_wca_hi, g_wca_hi);
    cudaGetSymbolAddress((void**)&p_wca_lo, g_wca_lo);

    // (1) embeddings
    embed_kernel<<<BB*SS, 256>>>(q, c, r, que_emb, concept_emb);
    // (2) w_ih split
    cvt_split<<<(1024*1024/4 + 255)/256, 256>>>(w_ih, p_wih_hi, p_wih_lo, 1024*1024);
    // (3) gx = qca @ w_ih^T + b_ih + b_hh
    { dim3 g(8, 50); mma_gemm<<<g, 256, GEMM_SMEM>>>(p_qca_hi, p_qca_lo, p_wih_hi, p_wih_lo,
                                                     b_ih, b_hh, p_gx, MTOT, 1024, 1024, 0); }
    // (4) LSTM  <-- profiled launch slot
    lstm_kernel<<<128, 256>>>(w_hh);
    // (5) hnext assembly
    hnext_kernel<<<MTOT, 256>>>();
    // (6-9) weight splits
    cvt_split<<<(768*768/4 + 255)/256, 256>>>(qn_lw, p_wqn_hi, p_wqn_lo, 768*768);
    cvt_split<<<(768*768/4 + 255)/256, 256>>>(cn_lw, p_wcn_hi, p_wcn_lo, 768*768);
    cvt_split<<<(256*256/4 + 255)/256, 256>>>(qa_lw, p_wqa_hi, p_wqa_lo, 256*256);
    cvt_split<<<(256*256/4 + 255)/256, 256>>>(ca_lw, p_wca_hi, p_wca_lo, 256*256);
    // (10-13) hidden GEMMs
    { dim3 g(6, 50); mma_gemm<<<g, 256, GEMM_SMEM>>>(p_hnx_hi, p_hnx_lo, p_wqn_hi, p_wqn_lo,
                                                     qn_lb, nullptr, p_hq, MTOT, 768, 768, 1); }
    { dim3 g(6, 50); mma_gemm<<<g, 256, GEMM_SMEM>>>(p_hnx_hi, p_hnx_lo, p_wcn_hi, p_wcn_lo,
                                                     cn_lb, nullptr, p_hc, MTOT, 768, 768, 1); }
    { dim3 g(2, 50); mma_gemm<<<g, 256, GEMM_SMEM>>>(p_hal_hi, p_hal_lo, p_wqa_hi, p_wqa_lo,
                                                     qa_lb, nullptr, p_hqa, MTOT, 256, 256, 1); }
    { dim3 g(2, 50); mma_gemm<<<g, 256, GEMM_SMEM>>>(p_hal_hi, p_hal_lo, p_wca_hi, p_wca_lo,
                                                     ca_lb, nullptr, p_hca, MTOT, 256, 256, 1); }
    // (14) gathered heads
    gather_kernel<<<MTOT/8, 256>>>(qshft, cshft, qn_ow, qn_ob, cn_ow, cn_ob,
                                   qa_ow, qa_ob, ca_ow, ca_ob, out);
    (void)in_sizes; (void)n_in; (void)out_size;
}